// round 16
// baseline (speedup 1.0000x reference)
#include <cuda_runtime.h>
#include <cstdint>

// Problem constants (fixed by the dataset)
#define B_  64
#define NH  1024
#define NV  2048

#define THREADS   128
#define VT        (THREADS * 4)   // 512 v-columns per block (float4 per thread)
#define H_SPLIT   4
#define HS        (NH / H_SPLIT)  // 256 h per block

// out layout: [ b2 : B*NV floats ][ wt2 : B*NH*NV floats ]
#define B2_ELEMS  (B_ * NV)

// ---------------------------------------------------------------------------
// Kernel 1: seed b2 with b1 (b2 then receives atomic partial sums)
// ---------------------------------------------------------------------------
__global__ void init_b2_kernel(const float* __restrict__ b1,
                               float* __restrict__ out_b2) {
    int i = blockIdx.x * blockDim.x + threadIdx.x;   // float4 index
    const float4* src = reinterpret_cast<const float4*>(b1);
    float4*       dst = reinterpret_cast<float4*>(out_b2);
    if (i < B2_ELEMS / 4) dst[i] = src[i];
}

// ---------------------------------------------------------------------------
// Kernel 2: fused  wt2 = scale * wt1  and  b2 += sum_h coeff[h] * wt1[:,h,:]
//   grid: (NV/VT, H_SPLIT, B) = (4, 4, 64) = 1024 CTAs, 128 threads, 32 regs.
//   One float4 per thread: every warp access covers whole 128B lines on both
//   the wt1 read and wt2 write streams (full coalescence), ~28 warps/SM.
//   Runs at the mixed-stream HBM plateau (~6.2 TB/s). All alternative
//   geometries and hints (R2-R13) measured neutral or worse; this shape won
//   the harness replay-loop total on all three of its runs (178.3-178.5us).
// ---------------------------------------------------------------------------
__global__ __launch_bounds__(THREADS)
void fused_convert_kernel(const float* __restrict__ wt1,
                          const float* __restrict__ muh1,
                          const float* __restrict__ muh2,
                          const float* __restrict__ varh1,
                          const float* __restrict__ varh2,
                          float* __restrict__ out_b2,
                          float* __restrict__ out_wt2) {
    __shared__ float s_scale[HS];
    __shared__ float s_coeff[HS];

    const int b  = blockIdx.z;
    const int h0 = blockIdx.y * HS;
    const int v0 = blockIdx.x * VT + threadIdx.x * 4;

    // Precompute per-h scale and coeff for this h-range
    for (int i = threadIdx.x; i < HS; i += THREADS) {
        const int idx = b * NH + h0 + i;
        const float sc = sqrtf(varh1[idx]) * rsqrtf(varh2[idx]);
        s_scale[i] = sc;
        s_coeff[i] = fmaf(-sc, muh2[idx], muh1[idx]);
    }
    __syncthreads();

    // float4 pointers; h-stride in float4 units is NV/4
    const size_t base = ((size_t)(b * NH + h0) * NV + v0) >> 2;
    const float4* __restrict__ src = reinterpret_cast<const float4*>(wt1) + base;
    float4*       __restrict__ dst = reinterpret_cast<float4*>(out_wt2) + base;
    const int hstride = NV / 4;

    float4 acc = make_float4(0.f, 0.f, 0.f, 0.f);

    #pragma unroll 4
    for (int i = 0; i < HS; ++i) {
        const float4 w  = __ldg(src + (size_t)i * hstride);
        const float  sc = s_scale[i];
        const float  cf = s_coeff[i];

        acc.x = fmaf(w.x, cf, acc.x);
        acc.y = fmaf(w.y, cf, acc.y);
        acc.z = fmaf(w.z, cf, acc.z);
        acc.w = fmaf(w.w, cf, acc.w);

        float4 o;
        o.x = w.x * sc; o.y = w.y * sc; o.z = w.z * sc; o.w = w.w * sc;
        dst[(size_t)i * hstride] = o;
    }

    // Partial b2 contribution from this h-split (REDG, distinct addresses)
    float* b2p = out_b2 + (size_t)b * NV + v0;
    atomicAdd(b2p + 0, acc.x);
    atomicAdd(b2p + 1, acc.y);
    atomicAdd(b2p + 2, acc.z);
    atomicAdd(b2p + 3, acc.w);
}

// ---------------------------------------------------------------------------
// Launch
// Inputs (metadata order): b1, wt1, muh1, muh2, varh_diag1, varh_diag2
// Output: [b2 | wt2]
// ---------------------------------------------------------------------------
extern "C" void kernel_launch(void* const* d_in, const int* in_sizes, int n_in,
                              void* d_out, int out_size) {
    const float* b1    = (const float*)d_in[0];
    const float* wt1   = (const float*)d_in[1];
    const float* muh1  = (const float*)d_in[2];
    const float* muh2  = (const float*)d_in[3];
    const float* varh1 = (const float*)d_in[4];
    const float* varh2 = (const float*)d_in[5];

    float* out_b2  = (float*)d_out;
    float* out_wt2 = out_b2 + B2_ELEMS;

    init_b2_kernel<<<(B2_ELEMS / 4 + 255) / 256, 256>>>(b1, out_b2);

    dim3 grid(NV / VT, H_SPLIT, B_);
    fused_convert_kernel<<<grid, THREADS>>>(wt1, muh1, muh2, varh1, varh2,
                                            out_b2, out_wt2);
}

// round 17
// speedup vs baseline: 1.0102x; 1.0102x over previous
#include <cuda_runtime.h>
#include <cstdint>

// Problem constants (fixed by the dataset)
#define B_  64
#define NH  1024
#define NV  2048

#define THREADS   128
#define VT        (THREADS * 4)   // 512 v-columns per block (float4 per thread)
#define H_SPLIT   4
#define HS        (NH / H_SPLIT)  // 256 h per block

// out layout: [ b2 : B*NV floats ][ wt2 : B*NH*NV floats ]
#define B2_ELEMS  (B_ * NV)

// ---------------------------------------------------------------------------
// Kernel 1: seed b2 with b1 (b2 then receives atomic partial sums)
// ---------------------------------------------------------------------------
__global__ void init_b2_kernel(const float* __restrict__ b1,
                               float* __restrict__ out_b2) {
    int i = blockIdx.x * blockDim.x + threadIdx.x;   // float4 index
    const float4* src = reinterpret_cast<const float4*>(b1);
    float4*       dst = reinterpret_cast<float4*>(out_b2);
    if (i < B2_ELEMS / 4) dst[i] = src[i];
}

// ---------------------------------------------------------------------------
// Kernel 2: fused  wt2 = scale * wt1  and  b2 += sum_h coeff[h] * wt1[:,h,:]
//   grid: (NV/VT, H_SPLIT, B) = (4, 4, 64) = 1024 CTAs, 128 threads, 32 regs.
//   One float4 per thread: every warp access covers whole 128B lines on both
//   the wt1 read and wt2 write streams (full coalescence), ~28 warps/SM.
//   Runs at the mixed-stream HBM plateau (~6.2 TB/s). All alternative
//   geometries and hints (R2-R16) measured neutral or worse; this shape won
//   the harness replay-loop total on every run (178.3-180.0us).
// ---------------------------------------------------------------------------
__global__ __launch_bounds__(THREADS)
void fused_convert_kernel(const float* __restrict__ wt1,
                          const float* __restrict__ muh1,
                          const float* __restrict__ muh2,
                          const float* __restrict__ varh1,
                          const float* __restrict__ varh2,
                          float* __restrict__ out_b2,
                          float* __restrict__ out_wt2) {
    __shared__ float s_scale[HS];
    __shared__ float s_coeff[HS];

    const int b  = blockIdx.z;
    const int h0 = blockIdx.y * HS;
    const int v0 = blockIdx.x * VT + threadIdx.x * 4;

    // Precompute per-h scale and coeff for this h-range
    for (int i = threadIdx.x; i < HS; i += THREADS) {
        const int idx = b * NH + h0 + i;
        const float sc = sqrtf(varh1[idx]) * rsqrtf(varh2[idx]);
        s_scale[i] = sc;
        s_coeff[i] = fmaf(-sc, muh2[idx], muh1[idx]);
    }
    __syncthreads();

    // float4 pointers; h-stride in float4 units is NV/4
    const size_t base = ((size_t)(b * NH + h0) * NV + v0) >> 2;
    const float4* __restrict__ src = reinterpret_cast<const float4*>(wt1) + base;
    float4*       __restrict__ dst = reinterpret_cast<float4*>(out_wt2) + base;
    const int hstride = NV / 4;

    float4 acc = make_float4(0.f, 0.f, 0.f, 0.f);

    #pragma unroll 4
    for (int i = 0; i < HS; ++i) {
        const float4 w  = __ldg(src + (size_t)i * hstride);
        const float  sc = s_scale[i];
        const float  cf = s_coeff[i];

        acc.x = fmaf(w.x, cf, acc.x);
        acc.y = fmaf(w.y, cf, acc.y);
        acc.z = fmaf(w.z, cf, acc.z);
        acc.w = fmaf(w.w, cf, acc.w);

        float4 o;
        o.x = w.x * sc; o.y = w.y * sc; o.z = w.z * sc; o.w = w.w * sc;
        dst[(size_t)i * hstride] = o;
    }

    // Partial b2 contribution from this h-split (REDG, distinct addresses)
    float* b2p = out_b2 + (size_t)b * NV + v0;
    atomicAdd(b2p + 0, acc.x);
    atomicAdd(b2p + 1, acc.y);
    atomicAdd(b2p + 2, acc.z);
    atomicAdd(b2p + 3, acc.w);
}

// ---------------------------------------------------------------------------
// Launch
// Inputs (metadata order): b1, wt1, muh1, muh2, varh_diag1, varh_diag2
// Output: [b2 | wt2]
// ---------------------------------------------------------------------------
extern "C" void kernel_launch(void* const* d_in, const int* in_sizes, int n_in,
                              void* d_out, int out_size) {
    const float* b1    = (const float*)d_in[0];
    const float* wt1   = (const float*)d_in[1];
    const float* muh1  = (const float*)d_in[2];
    const float* muh2  = (const float*)d_in[3];
    const float* varh1 = (const float*)d_in[4];
    const float* varh2 = (const float*)d_in[5];

    float* out_b2  = (float*)d_out;
    float* out_wt2 = out_b2 + B2_ELEMS;

    init_b2_kernel<<<(B2_ELEMS / 4 + 255) / 256, 256>>>(b1, out_b2);

    dim3 grid(NV / VT, H_SPLIT, B_);
    fused_convert_kernel<<<grid, THREADS>>>(wt1, muh1, muh2, varh1, varh2,
                                            out_b2, out_wt2);
}